// round 16
// baseline (speedup 1.0000x reference)
#include <cuda_runtime.h>
#include <cuda_fp16.h>
#include <math.h>

#define BB    128      // batch
#define TAPE  100000
#define NN    50000
#define FF    32
#define NTILE 32
#define GEMV_GRID   ((NN + NTILE - 1) / NTILE)   // 1563 gather blocks
#define COPY_BLOCKS 200                          // dedicated copy blocks

// Transposed tape in fp16: (TAPE, B). 25.6 MB static scratch -> L2-resident.
__device__ __align__(16) __half g_tapeTh[(size_t)TAPE * BB];

__device__ __forceinline__ float fast_tanh(float x) {
    float y;
    asm("tanh.approx.f32 %0, %1;" : "=f"(y) : "f"(x));
    return y;
}

// ---------------------------------------------------------------------------
// Kernel 1: pure transpose tape (B, TAPE) f32 -> g_tapeTh (TAPE, B) fp16.
// Read: float4 streaming loads. Write: half4 (STG.64), 4 iterations/thread.
// ---------------------------------------------------------------------------
__global__ void __launch_bounds__(256) transpose_kernel(
    const float* __restrict__ tape)
{
    __shared__ float tile[32][129];
    const int i0  = blockIdx.x * 128;
    const int b0  = blockIdx.y * 32;
    const int tx  = threadIdx.x;      // 0..31
    const int ty  = threadIdx.y;      // 0..7
    const int tid = ty * 32 + tx;
    const int wp  = tid >> 5;         // 0..7
    const int ln  = tid & 31;

#pragma unroll
    for (int r = 0; r < 32; r += 8) {
        const int b  = b0 + ty + r;
        const int gi = i0 + tx * 4;
        if (gi < TAPE) {
            float4 v = __ldcs(reinterpret_cast<const float4*>(
                tape + (size_t)b * TAPE + gi));
            tile[ty + r][tx * 4 + 0] = v.x;
            tile[ty + r][tx * 4 + 1] = v.y;
            tile[ty + r][tx * 4 + 2] = v.z;
            tile[ty + r][tx * 4 + 3] = v.w;
        }
    }
    __syncthreads();

    // write: lane handles 4 consecutive b (half4 store); warp covers 4 i-rows
    const int bq   = (ln & 7) * 4;    // 0,4,...,28
    const int isub = ln >> 3;         // 0..3
#pragma unroll
    for (int rr = 0; rr < 128; rr += 32) {
        const int il = rr + wp * 4 + isub;
        const int gi = i0 + il;
        if (gi < TAPE) {
            __half2 h01 = __floats2half2_rn(tile[bq + 0][il], tile[bq + 1][il]);
            __half2 h23 = __floats2half2_rn(tile[bq + 2][il], tile[bq + 3][il]);
            uint2 pk = make_uint2(*reinterpret_cast<unsigned int*>(&h01),
                                  *reinterpret_cast<unsigned int*>(&h23));
            *reinterpret_cast<uint2*>(&g_tapeTh[(size_t)gi * BB + b0 + bq]) = pk;
        }
    }
}

// ---------------------------------------------------------------------------
// Kernel 2: gather-GEMV + act + transposed store (blocks 0..GEMV_GRID-1),
// plus DEDICATED copy blocks (GEMV_GRID..GEMV_GRID+COPY_BLOCKS-1) that stream
// out[:, NN:) = tape[:, NN:) concurrently on idle DRAM bandwidth.
// Gather path identical to the R12 winner.
// ---------------------------------------------------------------------------
__global__ void __launch_bounds__(128, 6) gemv_kernel(
    const float* __restrict__ tape,
    const float* __restrict__ weights,
    const float* __restrict__ bias,
    const int*   __restrict__ in_idx,
    const int*   __restrict__ act,
    float*       __restrict__ out)
{
    __shared__ int2  s_iw[NTILE * FF];     // (index, f32 weight bits)
    __shared__ float s_b [NTILE];
    __shared__ int   s_a [NTILE];
    __shared__ float s_t [NTILE * 133];    // [n][b], odd pad -> CF reads

    const int tid  = threadIdx.x;

    // ---- dedicated copy blocks ---------------------------------------------
    if (blockIdx.x >= GEMV_GRID) {
        const int cb = blockIdx.x - GEMV_GRID;
        const int per_row = (TAPE - NN) / 4;                // 12500 float4
        const size_t total = (size_t)BB * per_row;          // 1.6M
        for (size_t g = (size_t)cb * 128 + tid; g < total;
             g += (size_t)COPY_BLOCKS * 128) {
            int b = (int)(g / per_row);
            int c = (int)(g % per_row);
            const float4* src = (const float4*)(tape + (size_t)b * TAPE + NN);
            float4*       dst = (float4*)(out  + (size_t)b * TAPE + NN);
            __stwt(dst + c, __ldcs(src + c));
        }
        return;
    }

    // ---- gather blocks (identical to R12 winner) ---------------------------
    const int lane = tid & 31;
    const int wrp  = tid >> 5;             // 0..3
    const int lid  = lane & 15;
    const int hw   = lane >> 4;
    const int n0   = blockIdx.x * NTILE;
    const int nmax = (NN - n0 < NTILE) ? (NN - n0) : NTILE;

    for (int k = tid; k < nmax * FF; k += 128) {
        s_iw[k] = make_int2(in_idx[(size_t)n0 * FF + k],
                            __float_as_int(weights[(size_t)n0 * FF + k]));
    }
    if (tid < nmax) {
        s_b[tid] = bias[n0 + tid];
        s_a[tid] = act[n0 + tid];
    }
    __syncthreads();

    const __half* __restrict__ tT = g_tapeTh;

    for (int p = 0; p < 4; p++) {
        const int nn = 8 * p + 2 * wrp + hw;
        if (nn >= nmax) break;

        float a0 = 0.f, a1 = 0.f, a2 = 0.f, a3 = 0.f;
        float a4 = 0.f, a5 = 0.f, a6 = 0.f, a7 = 0.f;

#pragma unroll
        for (int f = 0; f < FF; f++) {
            const int2  iw  = s_iw[nn * FF + f];
            const float wgt = __int_as_float(iw.y);
            uint4 v = *reinterpret_cast<const uint4*>(
                tT + ((size_t)iw.x << 7) + lid * 8);
            float2 f01 = __half22float2(*reinterpret_cast<__half2*>(&v.x));
            float2 f23 = __half22float2(*reinterpret_cast<__half2*>(&v.y));
            float2 f45 = __half22float2(*reinterpret_cast<__half2*>(&v.z));
            float2 f67 = __half22float2(*reinterpret_cast<__half2*>(&v.w));
            a0 = fmaf(f01.x, wgt, a0);
            a1 = fmaf(f01.y, wgt, a1);
            a2 = fmaf(f23.x, wgt, a2);
            a3 = fmaf(f23.y, wgt, a3);
            a4 = fmaf(f45.x, wgt, a4);
            a5 = fmaf(f45.y, wgt, a5);
            a6 = fmaf(f67.x, wgt, a6);
            a7 = fmaf(f67.y, wgt, a7);
        }

        const float bv = s_b[nn];
        a0 += bv; a1 += bv; a2 += bv; a3 += bv;
        a4 += bv; a5 += bv; a6 += bv; a7 += bv;
        if (s_a[nn] == 0) {
            a0 = fmaxf(a0, 0.f); a1 = fmaxf(a1, 0.f);
            a2 = fmaxf(a2, 0.f); a3 = fmaxf(a3, 0.f);
            a4 = fmaxf(a4, 0.f); a5 = fmaxf(a5, 0.f);
            a6 = fmaxf(a6, 0.f); a7 = fmaxf(a7, 0.f);
        } else {
            a0 = fast_tanh(a0); a1 = fast_tanh(a1);
            a2 = fast_tanh(a2); a3 = fast_tanh(a3);
            a4 = fast_tanh(a4); a5 = fast_tanh(a5);
            a6 = fast_tanh(a6); a7 = fast_tanh(a7);
        }
        float* st = &s_t[nn * 133 + lid * 8];
        st[0] = a0; st[1] = a1; st[2] = a2; st[3] = a3;
        st[4] = a4; st[5] = a5; st[6] = a6; st[7] = a7;
    }
    __syncthreads();

    // coalesced transposed streaming write: out[b][n0+lane]
    if (lane < nmax) {
#pragma unroll 4
        for (int j = 0; j < 32; j++) {
            int bb = j * 4 + wrp;
            __stwt(&out[(size_t)bb * TAPE + n0 + lane], s_t[lane * 133 + bb]);
        }
    }
}

// ---------------------------------------------------------------------------
// Inputs (metadata order): tape f32, weights f32, bias f32,
//                          input_indices i32, output_indices i32, act_type i32
// output_indices == arange(N) -> dense column-block write.
// ---------------------------------------------------------------------------
extern "C" void kernel_launch(void* const* d_in, const int* in_sizes, int n_in,
                              void* d_out, int out_size) {
    const float* tape    = (const float*)d_in[0];
    const float* weights = (const float*)d_in[1];
    const float* bias    = (const float*)d_in[2];
    const int*   in_idx  = (const int*)d_in[3];
    const int*   act     = (const int*)d_in[5];
    float*       out     = (float*)d_out;

    dim3 tgrid((TAPE + 127) / 128, BB / 32);   // (782, 4)
    dim3 tblock(32, 8);
    transpose_kernel<<<tgrid, tblock>>>(tape);

    gemv_kernel<<<GEMV_GRID + COPY_BLOCKS, 128>>>(
        tape, weights, bias, in_idx, act, out);
}

// round 17
// speedup vs baseline: 1.5176x; 1.5176x over previous
#include <cuda_runtime.h>
#include <cuda_fp16.h>
#include <math.h>

#define BB    128      // batch
#define TAPE  100000
#define NN    50000
#define FF    32
#define NTILE 32

// Transposed tape in fp16: (TAPE, B). 25.6 MB static scratch -> L2-resident.
__device__ __align__(16) __half g_tapeTh[(size_t)TAPE * BB];

__device__ __forceinline__ float fast_tanh(float x) {
    float y;
    asm("tanh.approx.f32 %0, %1;" : "=f"(y) : "f"(x));
    return y;
}

// ---------------------------------------------------------------------------
// Kernel 1: fused transpose + passthrough copy (R12 structure).
//   reads tape (B, TAPE) f32 once (__ldcs);
//   writes g_tapeTh (TAPE, B) fp16 (keep in L2);
//   for gi >= NN also streams the float4 straight to out (__stwt).
// NEW: write phase uses half4 (STG.64) -> 4 iterations instead of 8.
// Banks: lane ln=8a+q reads tile[4q+j][base+a]; bank = 4q+j+a+c (129 ≡ 1
// mod 32) -> all 32 lanes distinct per j. Conflict-free.
// ---------------------------------------------------------------------------
__global__ void __launch_bounds__(256) transpose_copy_kernel(
    const float* __restrict__ tape, float* __restrict__ out)
{
    __shared__ float tile[32][129];
    const int i0  = blockIdx.x * 128;
    const int b0  = blockIdx.y * 32;
    const int tx  = threadIdx.x;      // 0..31
    const int ty  = threadIdx.y;      // 0..7
    const int tid = ty * 32 + tx;
    const int wp  = tid >> 5;         // 0..7
    const int ln  = tid & 31;

    // read phase: float4 streaming loads; fused copy-out for gi >= NN
#pragma unroll
    for (int r = 0; r < 32; r += 8) {
        const int b  = b0 + ty + r;
        const int gi = i0 + tx * 4;
        if (gi < TAPE) {
            float4 v = __ldcs(reinterpret_cast<const float4*>(
                tape + (size_t)b * TAPE + gi));
            tile[ty + r][tx * 4 + 0] = v.x;
            tile[ty + r][tx * 4 + 1] = v.y;
            tile[ty + r][tx * 4 + 2] = v.z;
            tile[ty + r][tx * 4 + 3] = v.w;
            if (gi >= NN)   // NN, i0 multiples of 4 -> whole-float4 granularity
                __stwt(reinterpret_cast<float4*>(out + (size_t)b * TAPE + gi), v);
        }
    }
    __syncthreads();

    // write phase: lane handles 4 consecutive b (half4 = STG.64);
    // warp covers 4 i-rows per iteration, 4 iterations total.
    const int bq   = (ln & 7) * 4;    // 0,4,...,28
    const int isub = ln >> 3;         // 0..3
#pragma unroll
    for (int rr = 0; rr < 128; rr += 32) {
        const int il = rr + wp * 4 + isub;
        const int gi = i0 + il;
        if (gi < TAPE) {
            __half2 h01 = __floats2half2_rn(tile[bq + 0][il], tile[bq + 1][il]);
            __half2 h23 = __floats2half2_rn(tile[bq + 2][il], tile[bq + 3][il]);
            uint2 pk = make_uint2(*reinterpret_cast<unsigned int*>(&h01),
                                  *reinterpret_cast<unsigned int*>(&h23));
            *reinterpret_cast<uint2*>(&g_tapeTh[(size_t)gi * BB + b0 + bq]) = pk;
        }
    }
}

// ---------------------------------------------------------------------------
// Kernel 2: fused gather-GEMV + activation + transposed store to out[:, 0:N)
// Byte-identical to the R12 winner (35.2us, ~94% of its L2 floor).
// Half-warp per n: lane loads uint4 (8 fp16 b) -> 16 lanes cover 128 b.
// ---------------------------------------------------------------------------
__global__ void __launch_bounds__(128, 6) gemv_kernel(
    const float* __restrict__ weights,
    const float* __restrict__ bias,
    const int*   __restrict__ in_idx,
    const int*   __restrict__ act,
    float*       __restrict__ out)
{
    __shared__ int2  s_iw[NTILE * FF];     // (index, f32 weight bits)
    __shared__ float s_b [NTILE];
    __shared__ int   s_a [NTILE];
    __shared__ float s_t [NTILE * 133];    // [n][b], odd pad -> CF reads

    const int tid  = threadIdx.x;
    const int lane = tid & 31;
    const int wrp  = tid >> 5;             // 0..3
    const int lid  = lane & 15;
    const int hw   = lane >> 4;
    const int n0   = blockIdx.x * NTILE;
    const int nmax = (NN - n0 < NTILE) ? (NN - n0) : NTILE;

    for (int k = tid; k < nmax * FF; k += 128) {
        s_iw[k] = make_int2(in_idx[(size_t)n0 * FF + k],
                            __float_as_int(weights[(size_t)n0 * FF + k]));
    }
    if (tid < nmax) {
        s_b[tid] = bias[n0 + tid];
        s_a[tid] = act[n0 + tid];
    }
    __syncthreads();

    const __half* __restrict__ tT = g_tapeTh;

    for (int p = 0; p < 4; p++) {
        const int nn = 8 * p + 2 * wrp + hw;
        if (nn >= nmax) break;

        float a0 = 0.f, a1 = 0.f, a2 = 0.f, a3 = 0.f;
        float a4 = 0.f, a5 = 0.f, a6 = 0.f, a7 = 0.f;

#pragma unroll
        for (int f = 0; f < FF; f++) {
            const int2  iw  = s_iw[nn * FF + f];
            const float wgt = __int_as_float(iw.y);
            uint4 v = *reinterpret_cast<const uint4*>(
                tT + ((size_t)iw.x << 7) + lid * 8);
            float2 f01 = __half22float2(*reinterpret_cast<__half2*>(&v.x));
            float2 f23 = __half22float2(*reinterpret_cast<__half2*>(&v.y));
            float2 f45 = __half22float2(*reinterpret_cast<__half2*>(&v.z));
            float2 f67 = __half22float2(*reinterpret_cast<__half2*>(&v.w));
            a0 = fmaf(f01.x, wgt, a0);
            a1 = fmaf(f01.y, wgt, a1);
            a2 = fmaf(f23.x, wgt, a2);
            a3 = fmaf(f23.y, wgt, a3);
            a4 = fmaf(f45.x, wgt, a4);
            a5 = fmaf(f45.y, wgt, a5);
            a6 = fmaf(f67.x, wgt, a6);
            a7 = fmaf(f67.y, wgt, a7);
        }

        const float bv = s_b[nn];
        a0 += bv; a1 += bv; a2 += bv; a3 += bv;
        a4 += bv; a5 += bv; a6 += bv; a7 += bv;
        if (s_a[nn] == 0) {
            a0 = fmaxf(a0, 0.f); a1 = fmaxf(a1, 0.f);
            a2 = fmaxf(a2, 0.f); a3 = fmaxf(a3, 0.f);
            a4 = fmaxf(a4, 0.f); a5 = fmaxf(a5, 0.f);
            a6 = fmaxf(a6, 0.f); a7 = fmaxf(a7, 0.f);
        } else {
            a0 = fast_tanh(a0); a1 = fast_tanh(a1);
            a2 = fast_tanh(a2); a3 = fast_tanh(a3);
            a4 = fast_tanh(a4); a5 = fast_tanh(a5);
            a6 = fast_tanh(a6); a7 = fast_tanh(a7);
        }
        float* st = &s_t[nn * 133 + lid * 8];
        st[0] = a0; st[1] = a1; st[2] = a2; st[3] = a3;
        st[4] = a4; st[5] = a5; st[6] = a6; st[7] = a7;
    }
    __syncthreads();

    // coalesced transposed streaming write: out[b][n0+lane]
    if (lane < nmax) {
#pragma unroll 4
        for (int j = 0; j < 32; j++) {
            int bb = j * 4 + wrp;
            __stwt(&out[(size_t)bb * TAPE + n0 + lane], s_t[lane * 133 + bb]);
        }
    }
}

// ---------------------------------------------------------------------------
// Inputs (metadata order): tape f32, weights f32, bias f32,
//                          input_indices i32, output_indices i32, act_type i32
// output_indices == arange(N) -> dense column-block write.
// ---------------------------------------------------------------------------
extern "C" void kernel_launch(void* const* d_in, const int* in_sizes, int n_in,
                              void* d_out, int out_size) {
    const float* tape    = (const float*)d_in[0];
    const float* weights = (const float*)d_in[1];
    const float* bias    = (const float*)d_in[2];
    const int*   in_idx  = (const int*)d_in[3];
    const int*   act     = (const int*)d_in[5];
    float*       out     = (float*)d_out;

    // 1) fused transpose (f32 -> fp16, (B,TAPE)->(TAPE,B)) + copy of out[:, N:)
    dim3 tgrid((TAPE + 127) / 128, BB / 32);   // (782, 4)
    dim3 tblock(32, 8);
    transpose_copy_kernel<<<tgrid, tblock>>>(tape, out);

    // 2) fused gather-GEMV + activation + write out[:, 0:N)
    int gblocks = (NN + NTILE - 1) / NTILE;    // 1563
    gemv_kernel<<<gblocks, 128>>>(weights, bias, in_idx, act, out);
}